// round 8
// baseline (speedup 1.0000x reference)
#include <cuda_runtime.h>

#define NQ       12
#define DIM      4096            // 2^12
#define NLAYERS  6
#define NGATES   (NLAYERS * NQ)  // 72
#define THREADS  128
#define APT      (DIM / THREADS) // 32 amplitudes per thread

typedef unsigned long long ull;

// Linear, invertible address swizzle. For every pass type the 5 lane-varying
// rep bits land injectively in address bits 0-4 -> conflict-free 32-bit LDS/STS.
__device__ __forceinline__ unsigned S2(unsigned p) {
    return p ^ ((p >> 4) & 0xFu) ^ (((p >> 8) & 1u) << 4);
}

// GF(2) matrices of the CNOT-chain map per layer (verified: rowA.colB = I,
// leading bit of cCOLB[l][q] is q). cROWA[l][j] = row j of T^l; cCOLB = col of T^-l.
__constant__ unsigned cROWA[NLAYERS + 1][NQ] = {
    {0x001,0x002,0x004,0x008,0x010,0x020,0x040,0x080,0x100,0x200,0x400,0x800},
    {0xFFF,0xFFE,0xFFC,0xFF8,0xFF0,0xFE0,0xFC0,0xF80,0xF00,0xE00,0xC00,0x800},
    {0x555,0xAAA,0x554,0xAA8,0x550,0xAA0,0x540,0xA80,0x500,0xA00,0x400,0x800},
    {0x333,0x666,0xCCC,0x998,0x330,0x660,0xCC0,0x980,0x300,0x600,0xC00,0x800},
    {0x111,0x222,0x444,0x888,0x110,0x220,0x440,0x880,0x100,0x200,0x400,0x800},
    {0xF0F,0xE1E,0xC3C,0x878,0x0F0,0x1E0,0x3C0,0x780,0xF00,0xE00,0xC00,0x800},
    {0x505,0xA0A,0x414,0x828,0x050,0x0A0,0x140,0x280,0x500,0xA00,0x400,0x800},
};
__constant__ unsigned cCOLB[NLAYERS][NQ] = {
    {0x001,0x002,0x004,0x008,0x010,0x020,0x040,0x080,0x100,0x200,0x400,0x800},
    {0x001,0x003,0x006,0x00C,0x018,0x030,0x060,0x0C0,0x180,0x300,0x600,0xC00},
    {0x001,0x002,0x005,0x00A,0x014,0x028,0x050,0x0A0,0x140,0x280,0x500,0xA00},
    {0x001,0x003,0x007,0x00F,0x01E,0x03C,0x078,0x0F0,0x1E0,0x3C0,0x780,0xF00},
    {0x001,0x002,0x004,0x008,0x011,0x022,0x044,0x088,0x110,0x220,0x440,0x880},
    {0x001,0x003,0x006,0x00C,0x019,0x033,0x066,0x0CC,0x198,0x330,0x660,0xCC0},
};

// ---- packed f32x2 primitives ----
__device__ __forceinline__ ull f2mul(ull a, ull b) {
    ull d; asm("mul.rn.f32x2 %0, %1, %2;" : "=l"(d) : "l"(a), "l"(b)); return d;
}
__device__ __forceinline__ ull f2fma(ull a, ull b, ull c) {
    ull d; asm("fma.rn.f32x2 %0, %1, %2, %3;" : "=l"(d) : "l"(a), "l"(b), "l"(c)); return d;
}
__device__ __forceinline__ ull pack2(float lo, float hi) {
    ull r; asm("mov.b64 %0, {%1, %2};" : "=l"(r) : "f"(lo), "f"(hi)); return r;
}
__device__ __forceinline__ void unpack2(ull v, float& lo, float& hi) {
    asm("mov.b64 {%0, %1}, %2;" : "=f"(lo), "=f"(hi) : "l"(v));
}

// Packed coefficients for one gate, oriented per lane-half (o in {0,3}: XGX = e^3).
struct Coef { ull gr[4], gn[4], gp[4]; };  // gr=Re(G), gn=-Im(G), gp=+Im(G), per entry

__device__ __forceinline__ Coef ldcoef(const float* __restrict__ sTab,
                                       int tb, unsigned o0, unsigned o1) {
    Coef c;
    #pragma unroll
    for (int e = 0; e < 4; e++) {
        c.gr[e] = pack2(sTab[tb +     (e ^ o0)], sTab[tb +     (e ^ o1)]);
        c.gn[e] = pack2(sTab[tb + 4 + (e ^ o0)], sTab[tb + 4 + (e ^ o1)]);
        c.gp[e] = pack2(sTab[tb + 8 + (e ^ o0)], sTab[tb + 8 + (e ^ o1)]);
    }
    return c;
}

// Complex 2x2 butterfly on a pair of groups packed in f32x2 lanes. 16 FFMA2, no swaps.
__device__ __forceinline__ void bfp(const Coef& c,
                                    ull& are, ull& aim, ull& bre, ull& bim) {
    ull yar = f2mul(c.gr[0], are);
    yar = f2fma(c.gn[0], aim, yar); yar = f2fma(c.gr[1], bre, yar); yar = f2fma(c.gn[1], bim, yar);
    ull yai = f2mul(c.gr[0], aim);
    yai = f2fma(c.gp[0], are, yai); yai = f2fma(c.gr[1], bim, yai); yai = f2fma(c.gp[1], bre, yai);
    ull ybr = f2mul(c.gr[2], are);
    ybr = f2fma(c.gn[2], aim, ybr); ybr = f2fma(c.gr[3], bre, ybr); ybr = f2fma(c.gn[3], bim, ybr);
    ull ybi = f2mul(c.gr[2], aim);
    ybi = f2fma(c.gp[2], are, ybi); ybi = f2fma(c.gr[3], bim, ybi); ybi = f2fma(c.gp[3], bre, ybi);
    are = yar; aim = yai; bre = ybr; bim = ybi;
}

__global__ __launch_bounds__(THREADS, 5)
void qsim_kernel(const float* __restrict__ x,
                 const float* __restrict__ params,
                 float* __restrict__ out) {
    __shared__ float  sRe[DIM], sIm[DIM];   // 32 KB: plane-split statevector, S2 layout
    __shared__ float  sTab[NGATES * 12];    // 3.4 KB: per gate [m*4+e], m: 0=gr,1=-gi,2=+gi
    __shared__ float  sc[NQ], ssn[NQ];      // cos(x/2), sin(x/2)
    __shared__ float2 sHi[64], sLo[64];     // product tables (qubits 0-5 / 6-11)
    __shared__ float  sExp[NQ];             // <Z_q> accumulators

    const int tid = threadIdx.x;
    const int b   = blockIdx.x;

    // ---- stage 0: trig + gate coefficient table ----
    if (tid < NQ) {
        float xv = x[b * NQ + tid];
        sc[tid]   = cosf(0.5f * xv);
        ssn[tid]  = sinf(0.5f * xv);
        sExp[tid] = 0.0f;
    }
    if (tid < NGATES) {
        float phi = params[tid * 3 + 0];
        float th  = params[tid * 3 + 1];
        float om  = params[tid * 3 + 2];
        float ct = cosf(0.5f * th), st = sinf(0.5f * th);
        float aa = 0.5f * (phi + om), bb = 0.5f * (phi - om);
        float ca = cosf(aa), sa = sinf(aa);
        float cb = cosf(bb), sb = sinf(bb);
        // Rot = [[ep*ct, -em*st], [conj(em)*st, conj(ep)*ct]], ep=ca-i sa, em=cb+i sb
        // entries e: 0=00, 1=01, 2=10, 3=11
        float gre[4] = { ca * ct, -cb * st,  cb * st,  ca * ct };
        float gim[4] = {-sa * ct, -sb * st, -sb * st,  sa * ct };
        int tb = tid * 12;
        #pragma unroll
        for (int e = 0; e < 4; e++) {
            sTab[tb + e]     =  gre[e];
            sTab[tb + 4 + e] = -gim[e];   // gn
            sTab[tb + 8 + e] =  gim[e];   // gp
        }
    }
    __syncthreads();

    // ---- stage 1: 6-qubit product tables ----
    if (tid < 64) {
        float2 v = make_float2(1.0f, 0.0f);
        float2 w = make_float2(1.0f, 0.0f);
        #pragma unroll
        for (int j = 0; j < 6; j++) {
            int bit = (tid >> (5 - j)) & 1;
            // qubit j for hi table
            v = bit ? make_float2(v.y * ssn[j], -v.x * ssn[j])
                    : make_float2(v.x * sc[j],   v.y * sc[j]);
            // qubit 6+j for lo table
            int q = 6 + j;
            w = bit ? make_float2(w.y * ssn[q], -w.x * ssn[q])
                    : make_float2(w.x * sc[q],   w.y * sc[q]);
        }
        sHi[tid] = v;
        sLo[tid] = w;
    }
    __syncthreads();

    // ---- stage 2: direct product-state init (RX embedding on |0..0>) ----
    #pragma unroll
    for (int lo = 0; lo < APT; lo++) {
        unsigned p = tid + lo * THREADS;
        float2 h  = sHi[p >> 6];
        float2 g  = sLo[p & 63];
        unsigned idx = S2(p);
        sRe[idx] = fmaf(h.x, g.x, -h.y * g.y);
        sIm[idx] = fmaf(h.x, g.y,  h.y * g.x);
    }
    __syncthreads();

    // ---- stage 3: 6 layers x 3 fused passes; CNOT chains folded into masks ----
    for (int l = 0; l < NLAYERS; l++) {
        #pragma unroll
        for (int pp = 0; pp < 3; pp++) {
            const int qp = pp * 4;
            const int jA = 11 - qp;
            const int pb = 8 - qp;                 // pivot block low bit: 8,4,0
            const unsigned mA = cCOLB[l][jA],     mB = cCOLB[l][jA - 1];
            const unsigned mC = cCOLB[l][jA - 2], mD = cCOLB[l][jA - 3];
            const unsigned rA = cROWA[l][jA],     rB = cROWA[l][jA - 1];
            const unsigned rC = cROWA[l][jA - 2], rD = cROWA[l][jA - 3];
            const unsigned wA = S2(mA), wB = S2(mB);
            const unsigned wC = S2(mC), wD = S2(mD);
            const unsigned lomask = (pb > 0) ? ((1u << pb) - 1u) : 0u;

            // two groups per thread, packed in f32x2 lanes
            const unsigned g0 = tid, g1 = tid + THREADS;
            const unsigned rep0 = ((g0 >> pb) << (pb + 4)) | (g0 & lomask);
            const unsigned rep1 = ((g1 >> pb) << (pb + 4)) | (g1 & lomask);
            const unsigned sb0 = S2(rep0), sb1 = S2(rep1);
            // orientation per gate per group (XGX <=> entry index XOR 3)
            const unsigned oA0 = (__popc(rA & rep0) & 1u) * 3u, oA1 = (__popc(rA & rep1) & 1u) * 3u;
            const unsigned oB0 = (__popc(rB & rep0) & 1u) * 3u, oB1 = (__popc(rB & rep1) & 1u) * 3u;
            const unsigned oC0 = (__popc(rC & rep0) & 1u) * 3u, oC1 = (__popc(rC & rep1) & 1u) * 3u;
            const unsigned oD0 = (__popc(rD & rep0) & 1u) * 3u, oD1 = (__popc(rD & rep1) & 1u) * 3u;

            ull vre[16], vim[16];
            #pragma unroll
            for (int k = 0; k < 16; k++) {
                unsigned off = ((k & 8) ? wA : 0u) ^ ((k & 4) ? wB : 0u)
                             ^ ((k & 2) ? wC : 0u) ^ ((k & 1) ? wD : 0u);
                unsigned a0 = sb0 ^ off, a1 = sb1 ^ off;
                vre[k] = pack2(sRe[a0], sRe[a1]);
                vim[k] = pack2(sIm[a0], sIm[a1]);
            }

            const int gid = l * NQ + qp;
            {   // gate A (group bit 3)
                Coef c = ldcoef(sTab, gid * 12, oA0, oA1);
                #pragma unroll
                for (int k = 0; k < 8; k++)
                    bfp(c, vre[k], vim[k], vre[k + 8], vim[k + 8]);
            }
            {   // gate B (group bit 2)
                Coef c = ldcoef(sTab, (gid + 1) * 12, oB0, oB1);
                #pragma unroll
                for (int h = 0; h < 16; h += 8)
                    #pragma unroll
                    for (int k = 0; k < 4; k++)
                        bfp(c, vre[h + k], vim[h + k], vre[h + k + 4], vim[h + k + 4]);
            }
            {   // gate C (group bit 1)
                Coef c = ldcoef(sTab, (gid + 2) * 12, oC0, oC1);
                #pragma unroll
                for (int h = 0; h < 16; h += 4)
                    #pragma unroll
                    for (int k = 0; k < 2; k++)
                        bfp(c, vre[h + k], vim[h + k], vre[h + k + 2], vim[h + k + 2]);
            }
            {   // gate D (group bit 0)
                Coef c = ldcoef(sTab, (gid + 3) * 12, oD0, oD1);
                #pragma unroll
                for (int k = 0; k < 16; k += 2)
                    bfp(c, vre[k], vim[k], vre[k + 1], vim[k + 1]);
            }

            #pragma unroll
            for (int k = 0; k < 16; k++) {
                unsigned off = ((k & 8) ? wA : 0u) ^ ((k & 4) ? wB : 0u)
                             ^ ((k & 2) ? wC : 0u) ^ ((k & 1) ? wD : 0u);
                unsigned a0 = sb0 ^ off, a1 = sb1 ^ off;
                float r0, r1, i0, i1;
                unpack2(vre[k], r0, r1);
                unpack2(vim[k], i0, i1);
                sRe[a0] = r0; sRe[a1] = r1;
                sIm[a0] = i0; sIm[a1] = i1;
            }
            __syncthreads();
        }
    }

    // ---- stage 4: probabilities -> <Z_q> with permuted sign masks ----
    // sign of Z_q at physical p = (-1)^parity(cROWA[6][11-q] & p)
    float e[NQ];
    #pragma unroll
    for (int q = 0; q < NQ; q++) e[q] = 0.0f;

    #pragma unroll
    for (int lo = 0; lo < APT; lo++) {
        unsigned p = tid + lo * THREADS;
        unsigned idx = S2(p);
        float re = sRe[idx], im = sIm[idx];
        float pr = fmaf(re, re, im * im);
        #pragma unroll
        for (int q = 0; q < NQ; q++)
            e[q] += (__popc(cROWA[NLAYERS][11 - q] & p) & 1) ? -pr : pr;
    }

    #pragma unroll
    for (int q = 0; q < NQ; q++) {
        float v = e[q];
        #pragma unroll
        for (int off = 16; off > 0; off >>= 1)
            v += __shfl_down_sync(0xffffffffu, v, off);
        if ((tid & 31) == 0) atomicAdd(&sExp[q], v);
    }
    __syncthreads();

    // ---- stage 5: readout mitigation, closed form ----
    // M = J - I => M^-1 = J/(n-1) - I ; out_q = (E+12)/11 - e_q - 2
    if (tid < NQ) {
        float E = 0.0f;
        #pragma unroll
        for (int q = 0; q < NQ; q++) E += sExp[q];
        out[b * NQ + tid] = (E + 12.0f) * (1.0f / 11.0f) - sExp[tid] - 2.0f;
    }
}

extern "C" void kernel_launch(void* const* d_in, const int* in_sizes, int n_in,
                              void* d_out, int out_size) {
    const float* x      = (const float*)d_in[0];
    const float* params = (const float*)d_in[1];
    if (n_in >= 2 && in_sizes[0] == NLAYERS * NQ * 3) {
        x      = (const float*)d_in[1];
        params = (const float*)d_in[0];
    }
    cudaFuncSetAttribute(qsim_kernel,
                         cudaFuncAttributePreferredSharedMemoryCarveout, 100);
    int nblk = out_size / NQ;   // 768
    qsim_kernel<<<nblk, THREADS>>>(x, params, (float*)d_out);
}

// round 9
// speedup vs baseline: 2.3972x; 2.3972x over previous
#include <cuda_runtime.h>

#define NQ       12
#define DIM      4096            // 2^12
#define NLAYERS  6
#define NGATES   (NLAYERS * NQ)  // 72
#define THREADS  128
#define APT      (DIM / THREADS) // 32 amplitudes per thread

typedef unsigned long long ull;

// Bank-conflict-avoiding layout: amplitude p lives at sAmp[SWZ(p)].
// GF(2)-linear and invertible: SWZ(a^b) = SWZ(a)^SWZ(b).
#define SWZ(p) ((p) ^ (((p) >> 4) & 0xFu))

// GF(2) matrices of the CNOT-chain map per layer (verified: rowA.colB = I,
// leading bit of cCOLB[l][q] is q). cROWA[l][j] = row j of T^l; cCOLB = col of T^-l.
__constant__ unsigned cROWA[NLAYERS + 1][NQ] = {
    {0x001,0x002,0x004,0x008,0x010,0x020,0x040,0x080,0x100,0x200,0x400,0x800},
    {0xFFF,0xFFE,0xFFC,0xFF8,0xFF0,0xFE0,0xFC0,0xF80,0xF00,0xE00,0xC00,0x800},
    {0x555,0xAAA,0x554,0xAA8,0x550,0xAA0,0x540,0xA80,0x500,0xA00,0x400,0x800},
    {0x333,0x666,0xCCC,0x998,0x330,0x660,0xCC0,0x980,0x300,0x600,0xC00,0x800},
    {0x111,0x222,0x444,0x888,0x110,0x220,0x440,0x880,0x100,0x200,0x400,0x800},
    {0xF0F,0xE1E,0xC3C,0x878,0x0F0,0x1E0,0x3C0,0x780,0xF00,0xE00,0xC00,0x800},
    {0x505,0xA0A,0x414,0x828,0x050,0x0A0,0x140,0x280,0x500,0xA00,0x400,0x800},
};
__constant__ unsigned cCOLB[NLAYERS][NQ] = {
    {0x001,0x002,0x004,0x008,0x010,0x020,0x040,0x080,0x100,0x200,0x400,0x800},
    {0x001,0x003,0x006,0x00C,0x018,0x030,0x060,0x0C0,0x180,0x300,0x600,0xC00},
    {0x001,0x002,0x005,0x00A,0x014,0x028,0x050,0x0A0,0x140,0x280,0x500,0xA00},
    {0x001,0x003,0x007,0x00F,0x01E,0x03C,0x078,0x0F0,0x1E0,0x3C0,0x780,0xF00},
    {0x001,0x002,0x004,0x008,0x011,0x022,0x044,0x088,0x110,0x220,0x440,0x880},
    {0x001,0x003,0x006,0x00C,0x019,0x033,0x066,0x0CC,0x198,0x330,0x660,0xCC0},
};

// ---- packed f32x2 primitives (Blackwell FFMA2 path) ----
__device__ __forceinline__ ull f2mul(ull a, ull b) {
    ull d; asm("mul.rn.f32x2 %0, %1, %2;" : "=l"(d) : "l"(a), "l"(b)); return d;
}
__device__ __forceinline__ ull f2fma(ull a, ull b, ull c) {
    ull d; asm("fma.rn.f32x2 %0, %1, %2, %3;" : "=l"(d) : "l"(a), "l"(b), "l"(c)); return d;
}
__device__ __forceinline__ ull f2swap(ull v) {  // (re,im) -> (im,re)
    ull d;
    asm("{\n\t.reg .b32 lo, hi;\n\tmov.b64 {lo, hi}, %1;\n\tmov.b64 %0, {hi, lo};\n\t}"
        : "=l"(d) : "l"(v));
    return d;
}
__device__ __forceinline__ ull packf2(float lo, float hi) {
    return (ull)__float_as_uint(lo) | ((ull)__float_as_uint(hi) << 32);
}

// One complex 2x2 butterfly on packed (re,im) amplitudes.
// Exploits Rot symmetry: G11 = conj(G00), G10 = -conj(G01):
//   y0 = r0.x0 + im.s0 + rm.x1 + i1.s1
//   y1 = ra.x0 + i1.s0 + r0.x1 + ia.s1
__device__ __forceinline__ void bf(ull& x0, ull& x1,
                                   ull r0, ull im, ull rm, ull i1v,
                                   ull ra, ull ia) {
    ull s0 = f2swap(x0), s1 = f2swap(x1);
    ull o0 = f2mul(r0, x0);
    o0 = f2fma(im,  s0, o0);
    o0 = f2fma(rm,  x1, o0);
    o0 = f2fma(i1v, s1, o0);
    ull o1 = f2mul(ra, x0);
    o1 = f2fma(i1v, s0, o1);
    o1 = f2fma(r0,  x1, o1);
    o1 = f2fma(ia,  s1, o1);
    x0 = o0; x1 = o1;
}

__global__ __launch_bounds__(THREADS, 6)
void qsim_kernel(const float* __restrict__ x,
                 const float* __restrict__ params,
                 float* __restrict__ out) {
    __shared__ ull    sAmp[DIM];            // 32 KB statevector, packed (re,im), swizzled
    __shared__ ull    sGateP[NGATES * 6];   // 3.4 KB: {r0, i0, i0s, r1, r1n, i1} per gate
    __shared__ float  sc[NQ], ssn[NQ];      // cos(x/2), sin(x/2)
    __shared__ float2 sL[32];               // product table, qubits 7..11
    __shared__ float  sExp[NQ];             // <Z_q> accumulators

    float2* sAmpF = reinterpret_cast<float2*>(sAmp);

    const int tid = threadIdx.x;
    const int b   = blockIdx.x;

    // ---- stage 0: trig + compressed packed gate table ----
    if (tid < NQ) {
        float xv = x[b * NQ + tid];
        sc[tid]   = cosf(0.5f * xv);
        ssn[tid]  = sinf(0.5f * xv);
        sExp[tid] = 0.0f;
    }
    if (tid < NGATES) {
        float phi = params[tid * 3 + 0];
        float th  = params[tid * 3 + 1];
        float om  = params[tid * 3 + 2];
        float ct = cosf(0.5f * th), st = sinf(0.5f * th);
        float aa = 0.5f * (phi + om), bb = 0.5f * (phi - om);
        float ca = cosf(aa), sa = sinf(aa);
        float cb = cosf(bb), sb = sinf(bb);
        // G00 = (gr0, gi0) = (ca ct, -sa ct); G01 = (gr1, gi1) = (-cb st, -sb st)
        // G10 = -conj(G01); G11 = conj(G00)
        float gr0 = ca * ct, gi0 = -sa * ct;
        float gr1 = -cb * st, gi1 = -sb * st;
        int tb = tid * 6;
        sGateP[tb + 0] = packf2( gr0,  gr0);   // r0
        sGateP[tb + 1] = packf2(-gi0,  gi0);   // i0
        sGateP[tb + 2] = packf2( gi0, -gi0);   // i0s = swap(i0)  (i-coef of G11)
        sGateP[tb + 3] = packf2( gr1,  gr1);   // r1
        sGateP[tb + 4] = packf2(-gr1, -gr1);   // r1n (real of G10)
        sGateP[tb + 5] = packf2(-gi1,  gi1);   // i1  (i-coef of G01 and G10)
    }
    __syncthreads();

    // ---- stage 1: low-5-bit product table (qubits 7..11 <-> bits 4..0) ----
    if (tid < 32) {
        float2 v = make_float2(1.0f, 0.0f);
        #pragma unroll
        for (int j = 0; j < 5; j++) {
            int q   = 7 + j;
            int bit = (tid >> (4 - j)) & 1;
            v = bit ? make_float2(v.y * ssn[q], -v.x * ssn[q])  // v * (-i sin)
                    : make_float2(v.x * sc[q],   v.y * sc[q]);  // v * cos
        }
        sL[tid] = v;
    }
    __syncthreads();

    // ---- stage 2: direct product-state init (RX embedding on |0..0>) ----
    {
        float2 h = make_float2(1.0f, 0.0f);
        #pragma unroll
        for (int j = 0; j < 7; j++) {
            int bit = (tid >> (6 - j)) & 1;
            h = bit ? make_float2(h.y * ssn[j], -h.x * ssn[j])
                    : make_float2(h.x * sc[j],   h.y * sc[j]);
        }
        #pragma unroll
        for (int lo = 0; lo < 32; lo++) {
            unsigned p = tid * APT + lo;
            float2 g = sL[lo];
            float2 r = make_float2(fmaf(h.x, g.x, -h.y * g.y),
                                   fmaf(h.x, g.y,  h.y * g.x));
            sAmpF[SWZ(p)] = r;
        }
    }
    __syncthreads();

    // ---- stage 3: variational layers; 4 gates fused, CNOTs folded into masks ----
    // Invariant entering layer l: sPhys[p] = sLogical[(T^l) p].
    for (int l = 0; l < NLAYERS; l++) {
        #pragma unroll
        for (int qp = 0; qp < NQ; qp += 4) {
            const int jA = 11 - qp;
            const int pb = 8 - qp;                 // pivot block low bit: 8,4,0
            const unsigned mA = cCOLB[l][jA],     mB = cCOLB[l][jA - 1];
            const unsigned mC = cCOLB[l][jA - 2], mD = cCOLB[l][jA - 3];
            const unsigned rA = cROWA[l][jA],     rB = cROWA[l][jA - 1];
            const unsigned rC = cROWA[l][jA - 2], rD = cROWA[l][jA - 3];
            const unsigned wA = SWZ(mA), wB = SWZ(mB);
            const unsigned wC = SWZ(mC), wD = SWZ(mD);
            const unsigned lomask = (pb > 0) ? ((1u << pb) - 1u) : 0u;
            const int g6 = (l * NQ + qp) * 6;      // compressed-coeff base (gate A)

            #pragma unroll
            for (int it = 0; it < DIM / 16 / THREADS; it++) {  // 2 groups/thread
                unsigned g   = tid + it * THREADS;             // 8-bit coset id
                unsigned rep = ((g >> pb) << (pb + 4)) | (g & lomask);
                const unsigned sb = SWZ(rep);
                // coset parities: orientation selector per gate (independent)
                const unsigned cA = __popc(rA & rep) & 1u;
                const unsigned cB = __popc(rB & rep) & 1u;
                const unsigned cC = __popc(rC & rep) & 1u;
                const unsigned cD = __popc(rD & rep) & 1u;

                ull v[16];
                #pragma unroll
                for (int k = 0; k < 16; k++) {
                    unsigned off = ((k & 8) ? wA : 0u) ^ ((k & 4) ? wB : 0u)
                                 ^ ((k & 2) ? wC : 0u) ^ ((k & 1) ? wD : 0u);
                    v[k] = sAmp[sb ^ off];
                }
                {   // gate A (group bit 3); orientation via index shifts on 6-word table
                    ull r0 = sGateP[g6 + 0],        im = sGateP[g6 + 1 + cA];
                    ull ia = sGateP[g6 + 2 - cA],   rm = sGateP[g6 + 3 + cA];
                    ull ra = sGateP[g6 + 4 - cA],   i1 = sGateP[g6 + 5];
                    #pragma unroll
                    for (int k = 0; k < 8; k++)
                        bf(v[k], v[k + 8], r0, im, rm, i1, ra, ia);
                }
                {   // gate B (group bit 2)
                    const int gb = g6 + 6;
                    ull r0 = sGateP[gb + 0],        im = sGateP[gb + 1 + cB];
                    ull ia = sGateP[gb + 2 - cB],   rm = sGateP[gb + 3 + cB];
                    ull ra = sGateP[gb + 4 - cB],   i1 = sGateP[gb + 5];
                    #pragma unroll
                    for (int h = 0; h < 16; h += 8)
                        #pragma unroll
                        for (int k = 0; k < 4; k++)
                            bf(v[h + k], v[h + k + 4], r0, im, rm, i1, ra, ia);
                }
                {   // gate C (group bit 1)
                    const int gb = g6 + 12;
                    ull r0 = sGateP[gb + 0],        im = sGateP[gb + 1 + cC];
                    ull ia = sGateP[gb + 2 - cC],   rm = sGateP[gb + 3 + cC];
                    ull ra = sGateP[gb + 4 - cC],   i1 = sGateP[gb + 5];
                    #pragma unroll
                    for (int h = 0; h < 16; h += 4)
                        #pragma unroll
                        for (int k = 0; k < 2; k++)
                            bf(v[h + k], v[h + k + 2], r0, im, rm, i1, ra, ia);
                }
                {   // gate D (group bit 0)
                    const int gb = g6 + 18;
                    ull r0 = sGateP[gb + 0],        im = sGateP[gb + 1 + cD];
                    ull ia = sGateP[gb + 2 - cD],   rm = sGateP[gb + 3 + cD];
                    ull ra = sGateP[gb + 4 - cD],   i1 = sGateP[gb + 5];
                    #pragma unroll
                    for (int k = 0; k < 16; k += 2)
                        bf(v[k], v[k + 1], r0, im, rm, i1, ra, ia);
                }
                #pragma unroll
                for (int k = 0; k < 16; k++) {
                    unsigned off = ((k & 8) ? wA : 0u) ^ ((k & 4) ? wB : 0u)
                                 ^ ((k & 2) ? wC : 0u) ^ ((k & 1) ? wD : 0u);
                    sAmp[sb ^ off] = v[k];
                }
            }
            __syncthreads();
        }
    }

    // ---- stage 4: probabilities -> <Z_q> with permuted sign masks ----
    // sign of Z_q at physical p = (-1)^parity(cROWA[6][11-q] & p)
    float e[NQ];
    #pragma unroll
    for (int q = 0; q < NQ; q++) e[q] = 0.0f;

    #pragma unroll
    for (int lo = 0; lo < APT; lo++) {
        unsigned p = tid + lo * THREADS;
        float2 a = sAmpF[SWZ(p)];
        float pr = fmaf(a.x, a.x, a.y * a.y);
        #pragma unroll
        for (int q = 0; q < NQ; q++)
            e[q] += (__popc(cROWA[NLAYERS][11 - q] & p) & 1) ? -pr : pr;
    }

    #pragma unroll
    for (int q = 0; q < NQ; q++) {
        float v = e[q];
        #pragma unroll
        for (int off = 16; off > 0; off >>= 1)
            v += __shfl_down_sync(0xffffffffu, v, off);
        if ((tid & 31) == 0) atomicAdd(&sExp[q], v);
    }
    __syncthreads();

    // ---- stage 5: readout mitigation, closed form ----
    // M = J - I => M^-1 = J/(n-1) - I ; out_q = (E+12)/11 - e_q - 2
    if (tid < NQ) {
        float E = 0.0f;
        #pragma unroll
        for (int q = 0; q < NQ; q++) E += sExp[q];
        out[b * NQ + tid] = (E + 12.0f) * (1.0f / 11.0f) - sExp[tid] - 2.0f;
    }
}

extern "C" void kernel_launch(void* const* d_in, const int* in_sizes, int n_in,
                              void* d_out, int out_size) {
    const float* x      = (const float*)d_in[0];
    const float* params = (const float*)d_in[1];
    if (n_in >= 2 && in_sizes[0] == NLAYERS * NQ * 3) {
        x      = (const float*)d_in[1];
        params = (const float*)d_in[0];
    }
    cudaFuncSetAttribute(qsim_kernel,
                         cudaFuncAttributePreferredSharedMemoryCarveout, 100);
    int nblk = out_size / NQ;   // 768
    qsim_kernel<<<nblk, THREADS>>>(x, params, (float*)d_out);
}